// round 14
// baseline (speedup 1.0000x reference)
#include <cuda_runtime.h>
#include <cuda_fp16.h>
#include <math.h>
#include <stdint.h>

#define BB 4
#define SS 2048
#define DD 1024
#define HH 16
#define WW 64
#define MM (BB*SS)   // 8192

// fp16 scratch
__device__ __half g_xh[(size_t)MM * DD];
__device__ __half g_wh[3][(size_t)DD * DD];
__device__ __half g_qkv[3][(size_t)MM * DD];

// ---------------------------------------------------------------------------
// PTX helpers
// ---------------------------------------------------------------------------
__device__ __forceinline__ uint32_t smem_u32(const void* p) {
    uint32_t a;
    asm("{ .reg .u64 t; cvta.to.shared.u64 t, %1; cvt.u32.u64 %0, t; }"
        : "=r"(a) : "l"(p));
    return a;
}
__device__ __forceinline__ void ldsm4(uint32_t* r, uint32_t a) {
    asm volatile("ldmatrix.sync.aligned.m8n8.x4.shared.b16 {%0,%1,%2,%3}, [%4];"
        : "=r"(r[0]), "=r"(r[1]), "=r"(r[2]), "=r"(r[3]) : "r"(a));
}
__device__ __forceinline__ void ldsm4t(uint32_t* r, uint32_t a) {
    asm volatile("ldmatrix.sync.aligned.m8n8.x4.trans.shared.b16 {%0,%1,%2,%3}, [%4];"
        : "=r"(r[0]), "=r"(r[1]), "=r"(r[2]), "=r"(r[3]) : "r"(a));
}
// D += A(16x16) * B(16x8), fp16 in, fp32 accum
__device__ __forceinline__ void mma16(float* c, const uint32_t* a,
                                      uint32_t b0, uint32_t b1) {
    asm volatile(
        "mma.sync.aligned.m16n8k16.row.col.f32.f16.f16.f32 "
        "{%0,%1,%2,%3}, {%4,%5,%6,%7}, {%8,%9}, {%0,%1,%2,%3};"
        : "+f"(c[0]), "+f"(c[1]), "+f"(c[2]), "+f"(c[3])
        : "r"(a[0]), "r"(a[1]), "r"(a[2]), "r"(a[3]), "r"(b0), "r"(b1));
}
__device__ __forceinline__ void cpa16(uint32_t dst, const void* src) {
    asm volatile("cp.async.cg.shared.global [%0], [%1], 16;"
                 :: "r"(dst), "l"(src));
}
__device__ __forceinline__ void cpa_commit() {
    asm volatile("cp.async.commit_group;" ::: "memory");
}
template<int N> __device__ __forceinline__ void cpa_wait() {
    asm volatile("cp.async.wait_group %0;" :: "n"(N) : "memory");
}
__device__ __forceinline__ uint32_t h2u(__half2 h) { return *(uint32_t*)&h; }
__device__ __forceinline__ uint32_t hex2(uint32_t x) {
    uint32_t r;
    asm("ex2.approx.f16x2 %0, %1;" : "=r"(r) : "r"(x));
    return r;
}
__device__ __forceinline__ uint32_t hadd2u(uint32_t a, uint32_t b) {
    uint32_t r;
    asm("add.f16x2 %0, %1, %2;" : "=r"(r) : "r"(a), "r"(b));
    return r;
}

// ---------------------------------------------------------------------------
// fp32 -> fp16 conversion, one flat launch for x, Wq, Wk, Wv
// ---------------------------------------------------------------------------
#define NX4 (MM * DD / 4)   // 2097152
#define NW4 (DD * DD / 4)   // 262144

__global__ void __launch_bounds__(256) cvt_all(
    const float* __restrict__ x,  const float* __restrict__ Wq,
    const float* __restrict__ Wk, const float* __restrict__ Wv)
{
    int i = blockIdx.x * blockDim.x + threadIdx.x;
    const float* s;
    __half* d;
    int off;
    if (i < NX4)                { s = x;  d = g_xh;    off = i; }
    else if (i < NX4 + NW4)     { s = Wq; d = g_wh[0]; off = i - NX4; }
    else if (i < NX4 + 2 * NW4) { s = Wk; d = g_wh[1]; off = i - NX4 - NW4; }
    else if (i < NX4 + 3 * NW4) { s = Wv; d = g_wh[2]; off = i - NX4 - 2 * NW4; }
    else return;
    float4 v = ((const float4*)s)[off];
    uint2 u;
    u.x = h2u(__floats2half2_rn(v.x, v.y));
    u.y = h2u(__floats2half2_rn(v.z, v.w));
    ((uint2*)d)[off] = u;
}

// ---------------------------------------------------------------------------
// QKV projection GEMM (exact R7-known-good config): 256 threads, 8 warps
// (4m x 2n), warp tile 32x64, fp16 mma + ldmatrix + 3-stage cp.async,
// one sync per K-chunk, prefetch at END of body. Q pre-scaled 0.125*log2e.
// ---------------------------------------------------------------------------
#define QST 72
#define QTILE (128 * QST)
#define LOG2E 1.44269504088896f

__global__ void __launch_bounds__(256) qkv_tc(
    const float* __restrict__ bq, const float* __restrict__ bk,
    const float* __restrict__ bv)
{
    extern __shared__ __half qsm[];   // [3 stages][A|B], QTILE halves each
    const int which = blockIdx.z;
    const __half* xh = g_xh;
    const __half* wh = g_wh[which];
    const float* bias = (which == 0) ? bq : (which == 1) ? bk : bv;
    const float oscale = (which == 0) ? (0.125f * LOG2E) : 1.0f;

    const int tid = threadIdx.x;
    const int lane = tid & 31;
    const int wid = tid >> 5;
    const int wm = wid & 3, wn = wid >> 2;
    const int lane4 = lane >> 2, lanem = lane & 3;
    const int g = lane >> 3, l7 = lane & 7;
    const int m0 = blockIdx.y * 128, n0 = blockIdx.x * 128;

    uint32_t uA[3], uB[3];
#pragma unroll
    for (int i = 0; i < 3; i++) {
        uA[i] = smem_u32(qsm + i * 2 * QTILE);
        uB[i] = smem_u32(qsm + i * 2 * QTILE + QTILE);
    }

    const int crow = tid >> 3, cq = tid & 7;

    auto issue = [&](int kc, int st) {
#pragma unroll
        for (int i = 0; i < 4; i++) {
            const int r = crow + i * 32;
            cpa16(uA[st] + (r * QST + cq * 8) * 2,
                  xh + (size_t)(m0 + r) * DD + kc * 64 + cq * 8);
            cpa16(uB[st] + (r * QST + cq * 8) * 2,
                  wh + (size_t)(n0 + r) * DD + kc * 64 + cq * 8);
        }
        cpa_commit();
    };

    float acc[2][8][4];
#pragma unroll
    for (int mt = 0; mt < 2; mt++)
#pragma unroll
        for (int nt = 0; nt < 8; nt++)
#pragma unroll
            for (int i = 0; i < 4; i++) acc[mt][nt][i] = 0.f;

    issue(0, 0);
    issue(1, 1);

    const int a_row = (g & 1) * 8 + l7;
    const int a_col = (g >> 1) * 8;
    const int b_row = (g >> 1) * 8 + l7;
    const int b_col = (g & 1) * 8;

    for (int kc = 0; kc < 16; kc++) {
        const int st = kc % 3;
        if (kc < 15) cpa_wait<1>(); else cpa_wait<0>();
        __syncthreads();
#pragma unroll
        for (int kt = 0; kt < 4; kt++) {
            uint32_t af[2][4];
#pragma unroll
            for (int mt = 0; mt < 2; mt++)
                ldsm4(af[mt], uA[st] +
                      ((wm * 32 + mt * 16 + a_row) * QST + kt * 16 + a_col) * 2);
#pragma unroll
            for (int ng = 0; ng < 4; ng++) {
                uint32_t bf[4];
                ldsm4(bf, uB[st] +
                      ((wn * 64 + ng * 16 + b_row) * QST + kt * 16 + b_col) * 2);
                mma16(acc[0][2 * ng],     af[0], bf[0], bf[1]);
                mma16(acc[0][2 * ng + 1], af[0], bf[2], bf[3]);
                mma16(acc[1][2 * ng],     af[1], bf[0], bf[1]);
                mma16(acc[1][2 * ng + 1], af[1], bf[2], bf[3]);
            }
        }
        // prefetch at END of body (R7 placement — fills the barrier shadow)
        if (kc + 2 < 16) issue(kc + 2, (kc + 2) % 3);
    }

    __half* outp = g_qkv[which];
#pragma unroll
    for (int mt = 0; mt < 2; mt++) {
#pragma unroll
        for (int half = 0; half < 2; half++) {
            const int m = m0 + wm * 32 + mt * 16 + lane4 + half * 8;
            const int b = m >> 11;
            const int s = m & (SS - 1);
#pragma unroll
            for (int nt = 0; nt < 8; nt++) {
                const int n = n0 + wn * 64 + nt * 8 + 2 * lanem;
                const int h = n >> 6, w = n & 63;
                float2 bvv = *(const float2*)&bias[n];
                __half2 v = __floats2half2_rn(
                    (acc[mt][nt][half * 2 + 0] + bvv.x) * oscale,
                    (acc[mt][nt][half * 2 + 1] + bvv.y) * oscale);
                *(__half2*)&outp[((size_t)((b * HH + h) * SS + s)) * WW + w] = v;
            }
        }
    }
}

// ---------------------------------------------------------------------------
// Attention: R7 pipeline, but each warp covers 32 q-rows (two m16 blocks) ->
// CTA = 256 q-rows, 8 warps, 256 threads. K/V ldsm per HMMA halves (B-frags
// shared by both m-blocks); K/V L2 traffic halves (8 CTAs/head not 16).
// No online max; Q pre-scaled 0.125*log2e; lsum via ones-column MMA.
// 3-stage cp.async, 1 sync per 64-key tile, prefetch at end of body.
// ---------------------------------------------------------------------------
#define AST 72
#define BUFH (64 * AST)   // halves per K-or-V buffer

__global__ void __launch_bounds__(256) attn_tc(
    const int* __restrict__ mask, float* __restrict__ out)
{
    extern __shared__ __half dsm[];
    // layout: [3 stages][K buf | V buf] then mask addend (SS halves)
    __half* sM2 = dsm + 6 * BUFH;

    const int tid = threadIdx.x;
    const int lane = tid & 31;
    const int wm = tid >> 5;            // warp owns q-rows [wm*32, wm*32+32)
    const int lane4 = lane >> 2, lanem = lane & 3;
    const int g = lane >> 3, l7 = lane & 7;
    const int b = blockIdx.z, h = blockIdx.y;
    const int s0 = blockIdx.x * 256;

    const __half* qg = g_qkv[0] + ((size_t)(b * HH + h) * SS + s0) * WW;
    const __half* kg = g_qkv[1] + (size_t)(b * HH + h) * SS * WW;
    const __half* vg = g_qkv[2] + (size_t)(b * HH + h) * SS * WW;

    uint32_t uK[3], uV[3];
#pragma unroll
    for (int i = 0; i < 3; i++) {
        uK[i] = smem_u32(dsm + i * 2 * BUFH);
        uV[i] = smem_u32(dsm + i * 2 * BUFH + BUFH);
    }
    const uint32_t ubase = smem_u32(dsm);

    // mask addend (log2 units) in fp16
#pragma unroll
    for (int i = tid; i < SS; i += 256)
        sM2[i] = __float2half(mask[b * SS + i] ? 0.f : (-10000.f * LOG2E));

    // stage Q (256 rows) across the first 4 K/V buffers, pull A-fragments
    {
#pragma unroll
        for (int i = 0; i < 8; i++) {
            const int idx = tid + i * 256;       // 0..2047
            const int row = idx >> 3, q = idx & 7;
            uint4 v = ((const uint4*)(qg + (size_t)row * WW))[q];
            *(uint4*)&dsm[(row >> 6) * BUFH + (row & 63) * AST + q * 8] = v;
        }
    }
    __syncthreads();

    uint32_t qf[2][4][4];   // [m-block][kt][frag]
#pragma unroll
    for (int mt = 0; mt < 2; mt++) {
        const int r = wm * 32 + mt * 16 + (g & 1) * 8 + l7;
#pragma unroll
        for (int kt = 0; kt < 4; kt++)
            ldsm4(qf[mt][kt], ubase +
                  ((r >> 6) * BUFH + (r & 63) * AST + kt * 16 + (g >> 1) * 8) * 2);
    }
    __syncthreads();   // all warps extracted Q before prefetch overwrites

    const int crow = tid >> 3, cq = tid & 7;
    auto issue = [&](int t0, int st) {
#pragma unroll
        for (int i = 0; i < 2; i++) {
            const int r = crow + i * 32;
            cpa16(uK[st] + (r * AST + cq * 8) * 2,
                  kg + (size_t)(t0 + r) * WW + cq * 8);
            cpa16(uV[st] + (r * AST + cq * 8) * 2,
                  vg + (size_t)(t0 + r) * WW + cq * 8);
        }
        cpa_commit();
    };

    issue(0, 0);
    issue(64, 1);

    float o[2][8][4];       // [m-block][n-tile][frag]
#pragma unroll
    for (int mt = 0; mt < 2; mt++)
#pragma unroll
        for (int nt = 0; nt < 8; nt++)
#pragma unroll
            for (int i = 0; i < 4; i++) o[mt][nt][i] = 0.f;
    float lsum[2][4] = {{0.f, 0.f, 0.f, 0.f}, {0.f, 0.f, 0.f, 0.f}};
    const uint32_t ONE2 = 0x3C003C00u;

    const int kb_row = (g >> 1) * 8 + l7;
    const int kb_col = (g & 1) * 8;
    const int vb_row = (g & 1) * 8 + l7;
    const int vb_col = (g >> 1) * 8;

    for (int t = 0; t < 32; t++) {
        const int st = t % 3;
        if (t < 31) cpa_wait<1>(); else cpa_wait<0>();
        __syncthreads();

        const int t0 = t * 64;
        uint32_t pf[2][4][4];   // [m-block][ng][frag]

        // ---- QK + fused softmax, one 16-key group (ng) at a time ----
#pragma unroll
        for (int ng = 0; ng < 4; ng++) {
            float sA0[4] = {0.f, 0.f, 0.f, 0.f};
            float sA1[4] = {0.f, 0.f, 0.f, 0.f};
            float sB0[4] = {0.f, 0.f, 0.f, 0.f};
            float sB1[4] = {0.f, 0.f, 0.f, 0.f};
#pragma unroll
            for (int kt = 0; kt < 4; kt++) {
                uint32_t bf[4];
                ldsm4(bf, uK[st] +
                      ((ng * 16 + kb_row) * AST + kt * 16 + kb_col) * 2);
                mma16(sA0, qf[0][kt], bf[0], bf[1]);
                mma16(sA1, qf[0][kt], bf[2], bf[3]);
                mma16(sB0, qf[1][kt], bf[0], bf[1]);
                mma16(sB1, qf[1][kt], bf[2], bf[3]);
            }
            const uint32_t mk0 =
                *(const uint32_t*)&sM2[t0 + (2 * ng) * 8 + 2 * lanem];
            const uint32_t mk1 =
                *(const uint32_t*)&sM2[t0 + (2 * ng + 1) * 8 + 2 * lanem];
            pf[0][ng][0] = hex2(hadd2u(h2u(__floats2half2_rn(sA0[0], sA0[1])), mk0));
            pf[0][ng][1] = hex2(hadd2u(h2u(__floats2half2_rn(sA0[2], sA0[3])), mk0));
            pf[0][ng][2] = hex2(hadd2u(h2u(__floats2half2_rn(sA1[0], sA1[1])), mk1));
            pf[0][ng][3] = hex2(hadd2u(h2u(__floats2half2_rn(sA1[2], sA1[3])), mk1));
            pf[1][ng][0] = hex2(hadd2u(h2u(__floats2half2_rn(sB0[0], sB0[1])), mk0));
            pf[1][ng][1] = hex2(hadd2u(h2u(__floats2half2_rn(sB0[2], sB0[3])), mk0));
            pf[1][ng][2] = hex2(hadd2u(h2u(__floats2half2_rn(sB1[0], sB1[1])), mk1));
            pf[1][ng][3] = hex2(hadd2u(h2u(__floats2half2_rn(sB1[2], sB1[3])), mk1));
        }

        // ---- PV (B-fragments shared by both m-blocks) ----
#pragma unroll
        for (int kc = 0; kc < 4; kc++) {
#pragma unroll
            for (int ng = 0; ng < 4; ng++) {
                uint32_t bf[4];
                ldsm4t(bf, uV[st] +
                       ((kc * 16 + vb_row) * AST + ng * 16 + vb_col) * 2);
                mma16(o[0][2 * ng],     pf[0][kc], bf[0], bf[1]);
                mma16(o[0][2 * ng + 1], pf[0][kc], bf[2], bf[3]);
                mma16(o[1][2 * ng],     pf[1][kc], bf[0], bf[1]);
                mma16(o[1][2 * ng + 1], pf[1][kc], bf[2], bf[3]);
            }
        }

        // ---- row sums via ones-column MMA ----
#pragma unroll
        for (int kc = 0; kc < 4; kc++) {
            mma16(lsum[0], pf[0][kc], ONE2, ONE2);
            mma16(lsum[1], pf[1][kc], ONE2, ONE2);
        }

        // prefetch at END of body (R7 placement)
        if (t + 2 < 32) issue((t + 2) * 64, (t + 2) % 3);
    }

    // epilogue: normalize by row sums, write f32 (B,S,D)
#pragma unroll
    for (int mt = 0; mt < 2; mt++) {
        const float inv0 = 1.f / lsum[mt][0], inv1 = 1.f / lsum[mt][2];
        const int s_lo = s0 + wm * 32 + mt * 16 + lane4;
        const size_t base = ((size_t)(b * SS) + s_lo) * DD + h * WW + 2 * lanem;
#pragma unroll
        for (int nt = 0; nt < 8; nt++) {
            float2 v;
            v.x = o[mt][nt][0] * inv0; v.y = o[mt][nt][1] * inv0;
            *(float2*)&out[base + nt * 8] = v;
            v.x = o[mt][nt][2] * inv1; v.y = o[mt][nt][3] * inv1;
            *(float2*)&out[base + (size_t)8 * DD + nt * 8] = v;
        }
    }
}

// ---------------------------------------------------------------------------
extern "C" void kernel_launch(void* const* d_in, const int* in_sizes, int n_in,
                              void* d_out, int out_size)
{
    const float* x    = (const float*)d_in[0];
    const int*   mask = (const int*)  d_in[1];
    const float* Wq   = (const float*)d_in[2];
    const float* bq   = (const float*)d_in[3];
    const float* Wk   = (const float*)d_in[4];
    const float* bk   = (const float*)d_in[5];
    const float* Wv   = (const float*)d_in[6];
    const float* bv   = (const float*)d_in[7];
    float* out = (float*)d_out;

    const int ntot = NX4 + 3 * NW4;
    cvt_all<<<(ntot + 255) / 256, 256>>>(x, Wq, Wk, Wv);

    const int qdyn = 3 * 2 * QTILE * 2;            // 110592 bytes
    cudaFuncSetAttribute(qkv_tc, cudaFuncAttributeMaxDynamicSharedMemorySize, qdyn);
    const int adyn = (6 * BUFH + SS) * 2;          // 59392 bytes
    cudaFuncSetAttribute(attn_tc, cudaFuncAttributeMaxDynamicSharedMemorySize, adyn);

    dim3 g1(DD / 128, MM / 128, 3);   // (8, 64, 3)
    qkv_tc<<<g1, 256, qdyn>>>(bq, bk, bv);

    dim3 g2(SS / 256, HH, BB);        // (8, 16, 4)
    attn_tc<<<g2, 256, adyn>>>(mask, out);
}

// round 15
// speedup vs baseline: 1.0844x; 1.0844x over previous
#include <cuda_runtime.h>
#include <cuda_fp16.h>
#include <math.h>
#include <stdint.h>

#define BB 4
#define SS 2048
#define DD 1024
#define HH 16
#define WW 64
#define MM (BB*SS)   // 8192

// fp16 scratch
__device__ __half g_xh[(size_t)MM * DD];
__device__ __half g_wh[3][(size_t)DD * DD];
__device__ __half g_qkv[3][(size_t)MM * DD];

// ---------------------------------------------------------------------------
// PTX helpers
// ---------------------------------------------------------------------------
__device__ __forceinline__ uint32_t smem_u32(const void* p) {
    uint32_t a;
    asm("{ .reg .u64 t; cvta.to.shared.u64 t, %1; cvt.u32.u64 %0, t; }"
        : "=r"(a) : "l"(p));
    return a;
}
__device__ __forceinline__ void ldsm4(uint32_t* r, uint32_t a) {
    asm volatile("ldmatrix.sync.aligned.m8n8.x4.shared.b16 {%0,%1,%2,%3}, [%4];"
        : "=r"(r[0]), "=r"(r[1]), "=r"(r[2]), "=r"(r[3]) : "r"(a));
}
__device__ __forceinline__ void ldsm4t(uint32_t* r, uint32_t a) {
    asm volatile("ldmatrix.sync.aligned.m8n8.x4.trans.shared.b16 {%0,%1,%2,%3}, [%4];"
        : "=r"(r[0]), "=r"(r[1]), "=r"(r[2]), "=r"(r[3]) : "r"(a));
}
// D += A(16x16) * B(16x8), fp16 in, fp32 accum
__device__ __forceinline__ void mma16(float* c, const uint32_t* a,
                                      uint32_t b0, uint32_t b1) {
    asm volatile(
        "mma.sync.aligned.m16n8k16.row.col.f32.f16.f16.f32 "
        "{%0,%1,%2,%3}, {%4,%5,%6,%7}, {%8,%9}, {%0,%1,%2,%3};"
        : "+f"(c[0]), "+f"(c[1]), "+f"(c[2]), "+f"(c[3])
        : "r"(a[0]), "r"(a[1]), "r"(a[2]), "r"(a[3]), "r"(b0), "r"(b1));
}
__device__ __forceinline__ void cpa16(uint32_t dst, const void* src) {
    asm volatile("cp.async.cg.shared.global [%0], [%1], 16;"
                 :: "r"(dst), "l"(src));
}
__device__ __forceinline__ void cpa_commit() {
    asm volatile("cp.async.commit_group;" ::: "memory");
}
template<int N> __device__ __forceinline__ void cpa_wait() {
    asm volatile("cp.async.wait_group %0;" :: "n"(N) : "memory");
}
__device__ __forceinline__ uint32_t h2u(__half2 h) { return *(uint32_t*)&h; }
__device__ __forceinline__ uint32_t hex2(uint32_t x) {
    uint32_t r;
    asm("ex2.approx.f16x2 %0, %1;" : "=r"(r) : "r"(x));
    return r;
}
__device__ __forceinline__ uint32_t hadd2u(uint32_t a, uint32_t b) {
    uint32_t r;
    asm("add.f16x2 %0, %1, %2;" : "=r"(r) : "r"(a), "r"(b));
    return r;
}

// ---------------------------------------------------------------------------
// fp32 -> fp16 conversion, one flat launch for x, Wq, Wk, Wv
// ---------------------------------------------------------------------------
#define NX4 (MM * DD / 4)   // 2097152
#define NW4 (DD * DD / 4)   // 262144

__global__ void __launch_bounds__(256) cvt_all(
    const float* __restrict__ x,  const float* __restrict__ Wq,
    const float* __restrict__ Wk, const float* __restrict__ Wv)
{
    int i = blockIdx.x * blockDim.x + threadIdx.x;
    const float* s;
    __half* d;
    int off;
    if (i < NX4)                { s = x;  d = g_xh;    off = i; }
    else if (i < NX4 + NW4)     { s = Wq; d = g_wh[0]; off = i - NX4; }
    else if (i < NX4 + 2 * NW4) { s = Wk; d = g_wh[1]; off = i - NX4 - NW4; }
    else if (i < NX4 + 3 * NW4) { s = Wv; d = g_wh[2]; off = i - NX4 - 2 * NW4; }
    else return;
    float4 v = ((const float4*)s)[off];
    uint2 u;
    u.x = h2u(__floats2half2_rn(v.x, v.y));
    u.y = h2u(__floats2half2_rn(v.z, v.w));
    ((uint2*)d)[off] = u;
}

// ---------------------------------------------------------------------------
// QKV projection GEMM (exact R7-known-good config): 256 threads, 8 warps
// (4m x 2n), warp tile 32x64, fp16 mma + ldmatrix + 3-stage cp.async,
// one sync per K-chunk, prefetch at END of body. Q pre-scaled 0.125*log2e.
// ---------------------------------------------------------------------------
#define QST 72
#define QTILE (128 * QST)
#define LOG2E 1.44269504088896f

__global__ void __launch_bounds__(256) qkv_tc(
    const float* __restrict__ bq, const float* __restrict__ bk,
    const float* __restrict__ bv)
{
    extern __shared__ __half qsm[];   // [3 stages][A|B], QTILE halves each
    const int which = blockIdx.z;
    const __half* xh = g_xh;
    const __half* wh = g_wh[which];
    const float* bias = (which == 0) ? bq : (which == 1) ? bk : bv;
    const float oscale = (which == 0) ? (0.125f * LOG2E) : 1.0f;

    const int tid = threadIdx.x;
    const int lane = tid & 31;
    const int wid = tid >> 5;
    const int wm = wid & 3, wn = wid >> 2;
    const int lane4 = lane >> 2, lanem = lane & 3;
    const int g = lane >> 3, l7 = lane & 7;
    const int m0 = blockIdx.y * 128, n0 = blockIdx.x * 128;

    uint32_t uA[3], uB[3];
#pragma unroll
    for (int i = 0; i < 3; i++) {
        uA[i] = smem_u32(qsm + i * 2 * QTILE);
        uB[i] = smem_u32(qsm + i * 2 * QTILE + QTILE);
    }

    const int crow = tid >> 3, cq = tid & 7;

    auto issue = [&](int kc, int st) {
#pragma unroll
        for (int i = 0; i < 4; i++) {
            const int r = crow + i * 32;
            cpa16(uA[st] + (r * QST + cq * 8) * 2,
                  xh + (size_t)(m0 + r) * DD + kc * 64 + cq * 8);
            cpa16(uB[st] + (r * QST + cq * 8) * 2,
                  wh + (size_t)(n0 + r) * DD + kc * 64 + cq * 8);
        }
        cpa_commit();
    };

    float acc[2][8][4];
#pragma unroll
    for (int mt = 0; mt < 2; mt++)
#pragma unroll
        for (int nt = 0; nt < 8; nt++)
#pragma unroll
            for (int i = 0; i < 4; i++) acc[mt][nt][i] = 0.f;

    issue(0, 0);
    issue(1, 1);

    const int a_row = (g & 1) * 8 + l7;
    const int a_col = (g >> 1) * 8;
    const int b_row = (g >> 1) * 8 + l7;
    const int b_col = (g & 1) * 8;

    for (int kc = 0; kc < 16; kc++) {
        const int st = kc % 3;
        if (kc < 15) cpa_wait<1>(); else cpa_wait<0>();
        __syncthreads();
#pragma unroll
        for (int kt = 0; kt < 4; kt++) {
            uint32_t af[2][4];
#pragma unroll
            for (int mt = 0; mt < 2; mt++)
                ldsm4(af[mt], uA[st] +
                      ((wm * 32 + mt * 16 + a_row) * QST + kt * 16 + a_col) * 2);
#pragma unroll
            for (int ng = 0; ng < 4; ng++) {
                uint32_t bf[4];
                ldsm4(bf, uB[st] +
                      ((wn * 64 + ng * 16 + b_row) * QST + kt * 16 + b_col) * 2);
                mma16(acc[0][2 * ng],     af[0], bf[0], bf[1]);
                mma16(acc[0][2 * ng + 1], af[0], bf[2], bf[3]);
                mma16(acc[1][2 * ng],     af[1], bf[0], bf[1]);
                mma16(acc[1][2 * ng + 1], af[1], bf[2], bf[3]);
            }
        }
        // prefetch at END of body (R7 placement — fills the barrier shadow)
        if (kc + 2 < 16) issue(kc + 2, (kc + 2) % 3);
    }

    __half* outp = g_qkv[which];
#pragma unroll
    for (int mt = 0; mt < 2; mt++) {
#pragma unroll
        for (int half = 0; half < 2; half++) {
            const int m = m0 + wm * 32 + mt * 16 + lane4 + half * 8;
            const int b = m >> 11;
            const int s = m & (SS - 1);
#pragma unroll
            for (int nt = 0; nt < 8; nt++) {
                const int n = n0 + wn * 64 + nt * 8 + 2 * lanem;
                const int h = n >> 6, w = n & 63;
                float2 bvv = *(const float2*)&bias[n];
                __half2 v = __floats2half2_rn(
                    (acc[mt][nt][half * 2 + 0] + bvv.x) * oscale,
                    (acc[mt][nt][half * 2 + 1] + bvv.y) * oscale);
                *(__half2*)&outp[((size_t)((b * HH + h) * SS + s)) * WW + w] = v;
            }
        }
    }
}

// ---------------------------------------------------------------------------
// Attention: exact R7 body (ng-fused softmax, lsum ones-MMA, prefetch at end)
// with the pipeline deepened to 4 stages / prefetch distance 3 / wait<2>.
// No new live registers; arithmetic identical -> rel_err bit-identical.
// ---------------------------------------------------------------------------
#define AST 72
#define BUFH (64 * AST)   // halves per K-or-V buffer

__global__ void __launch_bounds__(256) attn_tc(
    const int* __restrict__ mask, float* __restrict__ out)
{
    extern __shared__ __half dsm[];
    // layout: [4 stages][K buf | V buf] then mask addend (SS halves)
    __half* sM2 = dsm + 8 * BUFH;

    const int tid = threadIdx.x;
    const int lane = tid & 31;
    const int wm = tid >> 5;
    const int lane4 = lane >> 2, lanem = lane & 3;
    const int g = lane >> 3, l7 = lane & 7;
    const int b = blockIdx.z, h = blockIdx.y;
    const int s0 = blockIdx.x * 128;

    const __half* qg = g_qkv[0] + ((size_t)(b * HH + h) * SS + s0) * WW;
    const __half* kg = g_qkv[1] + (size_t)(b * HH + h) * SS * WW;
    const __half* vg = g_qkv[2] + (size_t)(b * HH + h) * SS * WW;

    uint32_t uK[4], uV[4];
#pragma unroll
    for (int i = 0; i < 4; i++) {
        uK[i] = smem_u32(dsm + i * 2 * BUFH);
        uV[i] = smem_u32(dsm + i * 2 * BUFH + BUFH);
    }

    // mask addend (log2 units) in fp16
#pragma unroll
    for (int i = tid; i < SS; i += 256)
        sM2[i] = __float2half(mask[b * SS + i] ? 0.f : (-10000.f * LOG2E));

    // stage Q via stage-0 K/V buffers, pull A-fragments
    {
        const int crow = tid >> 1;
        const int cq0 = (tid & 1) * 4;
#pragma unroll
        for (int i = 0; i < 4; i++) {
            const int q = cq0 + i;
            uint4 v = ((const uint4*)(qg + (size_t)crow * WW))[q];
            __half* dst = (crow < 64) ? &dsm[crow * AST]
                                      : &dsm[BUFH + (crow - 64) * AST];
            *(uint4*)&dst[q * 8] = v;
        }
    }
    __syncthreads();

    uint32_t qf[4][4];
    {
        const uint32_t base = (wm < 4) ? uK[0] : uV[0];
        const int r0 = (wm & 3) * 16 + (g & 1) * 8 + l7;
#pragma unroll
        for (int kt = 0; kt < 4; kt++)
            ldsm4(qf[kt], base + (r0 * AST + kt * 16 + (g >> 1) * 8) * 2);
    }
    __syncthreads();

    const int crow = tid >> 3, cq = tid & 7;
    auto issue = [&](int t0, int st) {
#pragma unroll
        for (int i = 0; i < 2; i++) {
            const int r = crow + i * 32;
            cpa16(uK[st] + (r * AST + cq * 8) * 2,
                  kg + (size_t)(t0 + r) * WW + cq * 8);
            cpa16(uV[st] + (r * AST + cq * 8) * 2,
                  vg + (size_t)(t0 + r) * WW + cq * 8);
        }
        cpa_commit();
    };

    issue(0, 0);
    issue(64, 1);
    issue(128, 2);

    float o[8][4];
#pragma unroll
    for (int nt = 0; nt < 8; nt++)
#pragma unroll
        for (int i = 0; i < 4; i++) o[nt][i] = 0.f;
    float lsum[4] = {0.f, 0.f, 0.f, 0.f};
    const uint32_t ONE2 = 0x3C003C00u;

    const int kb_row = (g >> 1) * 8 + l7;
    const int kb_col = (g & 1) * 8;
    const int vb_row = (g & 1) * 8 + l7;
    const int vb_col = (g >> 1) * 8;

    for (int t = 0; t < 32; t++) {
        const int st = t & 3;
        // groups issued beyond t: 2 for t<=29, 1 at t=30, 0 at t=31.
        if (t <= 29)      cpa_wait<2>();
        else if (t == 30) cpa_wait<1>();
        else              cpa_wait<0>();
        __syncthreads();

        const int t0 = t * 64;
        uint32_t pf[4][4];

        // ---- QK + fused softmax, one 16-key group (ng) at a time ----
#pragma unroll
        for (int ng = 0; ng < 4; ng++) {
            float sc0[4] = {0.f, 0.f, 0.f, 0.f};
            float sc1[4] = {0.f, 0.f, 0.f, 0.f};
#pragma unroll
            for (int kt = 0; kt < 4; kt++) {
                uint32_t bf[4];
                ldsm4(bf, uK[st] +
                      ((ng * 16 + kb_row) * AST + kt * 16 + kb_col) * 2);
                mma16(sc0, qf[kt], bf[0], bf[1]);
                mma16(sc1, qf[kt], bf[2], bf[3]);
            }
            const uint32_t mk0 =
                *(const uint32_t*)&sM2[t0 + (2 * ng) * 8 + 2 * lanem];
            const uint32_t mk1 =
                *(const uint32_t*)&sM2[t0 + (2 * ng + 1) * 8 + 2 * lanem];
            pf[ng][0] = hex2(hadd2u(h2u(__floats2half2_rn(sc0[0], sc0[1])), mk0));
            pf[ng][1] = hex2(hadd2u(h2u(__floats2half2_rn(sc0[2], sc0[3])), mk0));
            pf[ng][2] = hex2(hadd2u(h2u(__floats2half2_rn(sc1[0], sc1[1])), mk1));
            pf[ng][3] = hex2(hadd2u(h2u(__floats2half2_rn(sc1[2], sc1[3])), mk1));
        }

        // ---- PV (feeds output accumulators, critical path) ----
#pragma unroll
        for (int kc = 0; kc < 4; kc++) {
#pragma unroll
            for (int ng = 0; ng < 4; ng++) {
                uint32_t bf[4];
                ldsm4t(bf, uV[st] +
                       ((kc * 16 + vb_row) * AST + ng * 16 + vb_col) * 2);
                mma16(o[2 * ng],     pf[kc], bf[0], bf[1]);
                mma16(o[2 * ng + 1], pf[kc], bf[2], bf[3]);
            }
        }

        // ---- row sums via ones-column MMA (only needed in epilogue) ----
#pragma unroll
        for (int kc = 0; kc < 4; kc++)
            mma16(lsum, pf[kc], ONE2, ONE2);

        // prefetch at END of body; stage (t+3)&3 was last read at t-1,
        // the sync at top of this iteration proves all warps finished it.
        if (t + 3 < 32) issue((t + 3) * 64, (t + 3) & 3);
    }

    // epilogue: normalize by row sums, write f32 (B,S,D)
    const float inv0 = 1.f / lsum[0], inv1 = 1.f / lsum[2];
    const int s_lo = s0 + wm * 16 + lane4;
    const size_t base = ((size_t)(b * SS) + s_lo) * DD + h * WW + 2 * lanem;
#pragma unroll
    for (int nt = 0; nt < 8; nt++) {
        float2 v;
        v.x = o[nt][0] * inv0; v.y = o[nt][1] * inv0;
        *(float2*)&out[base + nt * 8] = v;
        v.x = o[nt][2] * inv1; v.y = o[nt][3] * inv1;
        *(float2*)&out[base + (size_t)8 * DD + nt * 8] = v;
    }
}

// ---------------------------------------------------------------------------
extern "C" void kernel_launch(void* const* d_in, const int* in_sizes, int n_in,
                              void* d_out, int out_size)
{
    const float* x    = (const float*)d_in[0];
    const int*   mask = (const int*)  d_in[1];
    const float* Wq   = (const float*)d_in[2];
    const float* bq   = (const float*)d_in[3];
    const float* Wk   = (const float*)d_in[4];
    const float* bk   = (const float*)d_in[5];
    const float* Wv   = (const float*)d_in[6];
    const float* bv   = (const float*)d_in[7];
    float* out = (float*)d_out;

    const int ntot = NX4 + 3 * NW4;
    cvt_all<<<(ntot + 255) / 256, 256>>>(x, Wq, Wk, Wv);

    const int qdyn = 3 * 2 * QTILE * 2;            // 110592 bytes
    cudaFuncSetAttribute(qkv_tc, cudaFuncAttributeMaxDynamicSharedMemorySize, qdyn);
    const int adyn = (8 * BUFH + SS) * 2;          // 77824 bytes
    cudaFuncSetAttribute(attn_tc, cudaFuncAttributeMaxDynamicSharedMemorySize, adyn);

    dim3 g1(DD / 128, MM / 128, 3);   // (8, 64, 3)
    qkv_tc<<<g1, 256, qdyn>>>(bq, bk, bv);

    dim3 g2(SS / 128, HH, BB);        // (16, 16, 4)
    attn_tc<<<g2, 256, adyn>>>(mask, out);
}